// round 9
// baseline (speedup 1.0000x reference)
#include <cuda_runtime.h>
#include <math.h>
#include <stdint.h>

#define Bsz   64
#define Tlen  256
#define Din   128
#define Hd    1024
#define Ld    5
#define Cd    10
#define FourH 4096
#define Mrows (Tlen * Bsz)   // 16384
#define BHd   (Bsz * Hd)

// ---------------- scratch (static device globals; no allocs) ----------------
// xproj layout is GATE-INTERLEAVED: xproj[row][hcol][gate], gate order i,f,g,o
__device__ float g_xproj[(size_t)Mrows * FourH];   // 256 MB
__device__ float g_hseq0[(size_t)Mrows * Hd];      // 64 MB (tf32-prerounded)
__device__ float g_hseq1[(size_t)Mrows * Hd];      // 64 MB (tf32-prerounded)
__device__ float g_hfull[BHd];                     // full precision final h (head)
__device__ float g_hr[2 * BHd];                    // tf32-prerounded h, double buffer
__device__ float g_xtf[(size_t)Bsz * Tlen * Din];          // prerounded x
__device__ float g_wtf[(size_t)(Din + 4 * Hd) * FourH];    // prerounded TRANSPOSED Wx0|Wxs
__device__ unsigned g_sync[129 * 32];   // flags[b]=g_sync[b*32], release=g_sync[128*32]

// ---------------- PTX helpers ----------------
__device__ __forceinline__ uint32_t f2tf32(float f) {
    uint32_t u; asm("cvt.rna.tf32.f32 %0, %1;" : "=r"(u) : "f"(f)); return u;
}
__device__ __forceinline__ void ldsm_x4(uint32_t& r0, uint32_t& r1, uint32_t& r2,
                                        uint32_t& r3, uint32_t addr) {
    asm volatile("ldmatrix.sync.aligned.m8n8.x4.shared.b16 {%0,%1,%2,%3}, [%4];"
                 : "=r"(r0), "=r"(r1), "=r"(r2), "=r"(r3) : "r"(addr));
}
__device__ __forceinline__ void mma_tf32(float* d, uint32_t a0, uint32_t a1,
                                         uint32_t a2, uint32_t a3,
                                         uint32_t b0, uint32_t b1) {
    asm volatile("mma.sync.aligned.m16n8k8.row.col.f32.tf32.tf32.f32 "
                 "{%0,%1,%2,%3}, {%4,%5,%6,%7}, {%8,%9}, {%0,%1,%2,%3};"
                 : "+f"(d[0]), "+f"(d[1]), "+f"(d[2]), "+f"(d[3])
                 : "r"(a0), "r"(a1), "r"(a2), "r"(a3), "r"(b0), "r"(b1));
}
__device__ __forceinline__ void cp16(uint32_t dst, const void* src) {
    asm volatile("cp.async.cg.shared.global [%0], [%1], 16;" :: "r"(dst), "l"(src));
}
__device__ __forceinline__ void cp_commit() {
    asm volatile("cp.async.commit_group;");
}
template <int N>
__device__ __forceinline__ void cp_wait() {
    asm volatile("cp.async.wait_group %0;" :: "n"(N));
}

// ---------------- grid barrier: parallel flags + block-0 scanner ----------------
__device__ __forceinline__ void grid_sync(unsigned epoch) {
    __syncthreads();
    int tid = threadIdx.x;
    int bid = blockIdx.x;
    if (tid == 0) {
        __threadfence();
        asm volatile("st.release.gpu.global.u32 [%0], %1;"
                     :: "l"(&g_sync[bid * 32]), "r"(epoch) : "memory");
    }
    if (bid == 0) {
        if (tid < 128) {
            unsigned v;
            do {
                asm volatile("ld.acquire.gpu.global.u32 %0, [%1];"
                             : "=r"(v) : "l"(&g_sync[tid * 32]) : "memory");
            } while (v < epoch);
        }
        __syncthreads();
        if (tid == 0)
            asm volatile("st.release.gpu.global.u32 [%0], %1;"
                         :: "l"(&g_sync[128 * 32]), "r"(epoch) : "memory");
    } else {
        if (tid == 0) {
            unsigned v;
            do {
                asm volatile("ld.acquire.gpu.global.u32 %0, [%1];"
                             : "=r"(v) : "l"(&g_sync[128 * 32]) : "memory");
            } while (v < epoch);
        }
    }
    __syncthreads();
}

// ---------------- fast activations ----------------
__device__ __forceinline__ float sigmoid_f(float x) {
    return __fdividef(1.f, 1.f + __expf(-x));
}
__device__ __forceinline__ float tanh_f(float x) {
    float e = __expf(2.f * x);
    return 1.f - __fdividef(2.f, e + 1.f);
}

// ---------------- preround x ----------------
__global__ void preround_x(const float* __restrict__ x) {
    size_t nx = (size_t)Bsz * Tlen * Din;
    size_t stride = (size_t)gridDim.x * blockDim.x;
    for (size_t i = (size_t)blockIdx.x * blockDim.x + threadIdx.x; i < nx; i += stride)
        g_xtf[i] = __uint_as_float(f2tf32(x[i]));
}

// ---------------- tiled transpose + tf32 round: src[K][N] -> dst[N][K] ------
__global__ void transpose_tf32(const float* __restrict__ src, float* __restrict__ dst,
                               int K, int N) {
    __shared__ float tile[32][33];
    int kb = blockIdx.y * 32, nb = blockIdx.x * 32;
    int tx = threadIdx.x, ty = threadIdx.y;   // 32 x 8
    for (int i = ty; i < 32; i += 8)
        tile[i][tx] = src[(size_t)(kb + i) * N + nb + tx];
    __syncthreads();
    for (int i = ty; i < 32; i += 8)
        dst[(size_t)(nb + i) * K + kb + tx] = __uint_as_float(f2tf32(tile[tx][i]));
}

// ============================================================================
// Input projection GEMM (tf32, cp.async 3-stage pipeline, ldmatrix A and B)
//   Block tile 128(M) x 256(N), k-tile 32, 512 threads = 16 warps (2m x 8n).
//   W is pre-transposed n-major: Wt[n][k].
// ============================================================================
#define PBP 36
#define STG_F (128 * 32 + 256 * PBP)       // 13312 floats per stage
#define PROJ_SMEM (3 * STG_F * 4)          // 159744 B

__global__ __launch_bounds__(512) void proj_gemm_tc(
    const float* __restrict__ A, int stride_t, int stride_b, int K,
    const float* __restrict__ Wt, const float* __restrict__ bias)
{
    extern __shared__ float ps[];
    uint32_t sbase = (uint32_t)__cvta_generic_to_shared(ps);

    int tid  = threadIdx.x;
    int wid  = tid >> 5;
    int lane = tid & 31;
    int row0 = blockIdx.y * 128;
    int col0 = blockIdx.x * 256;

    int wm = wid & 1;          // m-group (64 rows)
    int wn = wid >> 1;         // n-group (32 cols)

    // A issue mapping
    int a_row = tid >> 2;
    int a_c2  = (tid & 3) * 2;
    int agrow = row0 + a_row;
    const float* Aptr = A + (size_t)(agrow >> 6) * stride_t
                          + (size_t)(agrow & 63) * stride_b;
    int a_sw0 = a_row * 32 + ((a_c2)     ^ (a_row & 7)) * 4;
    int a_sw1 = a_row * 32 + ((a_c2 + 1) ^ (a_row & 7)) * 4;

    // ldmatrix lane components (A)
    int lm_row = (lane & 7) + ((lane >> 3) & 1) * 8;
    int lm_cs  = lane >> 4;
    int lm_x   = lane & 7;

    // ldmatrix lane components (B): matrix idx m = lane>>3
    int b_m   = lane >> 3;          // 0..3
    int b_nt4 = b_m >> 1;           // sub n-tile within pair
    int b_kc  = b_m & 1;            // k chunk (0 or +4)
    int b_r   = lane & 7;           // row within 8

    float acc[4][4][4];
#pragma unroll
    for (int i = 0; i < 4; i++)
#pragma unroll
        for (int j = 0; j < 4; j++)
#pragma unroll
            for (int r = 0; r < 4; r++) acc[i][j][r] = 0.f;

    int ntiles = K >> 5;

    auto issue = [&](int stage, int kt) {
        if (kt < ntiles) {
            int kb = kt * 32;
            uint32_t as = sbase + (stage * STG_F) * 4;
            cp16(as + a_sw0 * 4, Aptr + kb + a_c2 * 4);
            cp16(as + a_sw1 * 4, Aptr + kb + (a_c2 + 1) * 4);
            uint32_t bsm = sbase + (stage * STG_F + 128 * 32) * 4;
#pragma unroll
            for (int i = 0; i < 4; i++) {
                int id = i * 512 + tid;
                int n = id >> 3, k4 = (id & 7) * 4;
                cp16(bsm + (n * PBP + k4) * 4,
                     Wt + (size_t)(col0 + n) * K + kb + k4);
            }
        }
        cp_commit();
    };

    issue(0, 0);
    issue(1, 1);

    for (int kt = 0; kt < ntiles; kt++) {
        cp_wait<1>();
        __syncthreads();
        int cur = kt % 3;
        issue((kt + 2) % 3, kt + 2);

        uint32_t asb = sbase + (cur * STG_F) * 4;
        uint32_t bsb = sbase + (cur * STG_F + 128 * 32) * 4;

#pragma unroll
        for (int kk = 0; kk < 4; kk++) {
            uint32_t bf[4][2];
#pragma unroll
            for (int np = 0; np < 2; np++) {
                int nrow = wn * 32 + (np * 2 + b_nt4) * 8 + b_r;
                uint32_t addr = bsb + (nrow * PBP + kk * 8 + b_kc * 4) * 4;
                ldsm_x4(bf[np * 2][0], bf[np * 2][1],
                        bf[np * 2 + 1][0], bf[np * 2 + 1][1], addr);
            }
#pragma unroll
            for (int mt = 0; mt < 4; mt++) {
                int arow = wm * 64 + mt * 16 + lm_row;
                int phys = (kk * 2 + lm_cs) ^ lm_x;
                uint32_t a0, a1, a2, a3;
                ldsm_x4(a0, a1, a2, a3, asb + (arow * 32 + phys * 4) * 4);
#pragma unroll
                for (int nt = 0; nt < 4; nt++)
                    mma_tf32(acc[mt][nt], a0, a1, a2, a3, bf[nt][0], bf[nt][1]);
            }
        }
    }

    // epilogue: add bias, store gate-interleaved
    int gate  = col0 >> 10;
    int hbase = col0 & 1023;
#pragma unroll
    for (int mt = 0; mt < 4; mt++) {
        int row = row0 + wm * 64 + mt * 16 + (lane >> 2);
#pragma unroll
        for (int nt = 0; nt < 4; nt++) {
            int nl = wn * 32 + nt * 8 + 2 * (lane & 3);
            float b0v = bias[col0 + nl];
            float b1v = bias[col0 + nl + 1];
            int hcol = hbase + nl;
            float* o0 = g_xproj + (size_t)row * FourH + hcol * 4 + gate;
            o0[0] = acc[mt][nt][0] + b0v;
            o0[4] = acc[mt][nt][1] + b1v;
            float* o1 = o0 + (size_t)8 * FourH;
            o1[0] = acc[mt][nt][2] + b0v;
            o1[4] = acc[mt][nt][3] + b1v;
        }
    }
}

// ============================================================================
// Persistent recurrent layer — grid barrier per step, long-burst k-loop
//   128 blocks x 512 threads; 16 warps = (gate g = wid&3) x (k-split s = wid>>2)
//   Per step: 4 iterations of k=64 per group, 3-slot cp.async ring,
//   ONE __syncthreads per iteration. c held in registers. t=0: z = xp (h==0).
//   pD (k-split partials) aliased onto ring slot 1.
// ============================================================================
#define RGPITCH 68                       // 64 k + 4 pad; row*68 % 32 = 4*row
#define RGSEG   (64 * RGPITCH)           // 4352 floats per group per slot
#define SLOT_F  (4 * RGSEG)              // 17408 floats per slot
#define PDPITCH 36
#define PDSEG   (64 * PDPITCH)           // 2304
#define REC_SMEM (3 * SLOT_F * 4)        // 208896 B

__global__ __launch_bounds__(512) void lstm_layer_tc(
    const float* __restrict__ Wh, int seqsel, int writeseq)
{
    extern __shared__ float rs[];
    float* pD = rs + SLOT_F;             // alias slot 1 (safe, see proof in theory)
    uint32_t sbase = (uint32_t)__cvta_generic_to_shared(rs);

    int tid  = threadIdx.x;
    int wid  = tid >> 5;
    int lane = tid & 31;
    int g    = wid & 3;        // gate
    int s    = wid >> 2;       // k-group (256 k each)
    int c0   = blockIdx.x * 8;

    // ---- Wh slice into registers as tf32 B-fragments ----
    uint32_t b0[32], b1[32];
    {
        const float* Wb = Wh + (size_t)(s * 256) * FourH + g * Hd + c0 + (lane >> 2);
#pragma unroll
        for (int j = 0; j < 32; j++) {
            int k = j * 8 + (lane & 3);
            b0[j] = f2tf32(Wb[(size_t)k * FourH]);
            b1[j] = f2tf32(Wb[(size_t)(k + 4) * FourH]);
        }
    }

    float* seq = seqsel ? g_hseq1 : g_hseq0;

    // staging map: gs = tid>>7 (group staged), q = tid&127 -> row, half
    int gs    = tid >> 7;
    int qq0   = tid & 127;
    int srow  = qq0 >> 1;
    int shalf = qq0 & 1;

    int lm_row = (lane & 7) + ((lane >> 3) & 1) * 8;
    int lm_k   = (lane >> 4) * 4;
    int gm = tid >> 3, ghc = tid & 7;
    int ghi = gm * Hd + c0 + ghc;

    float creg = 0.f;          // cell state in register (block/thread-private)
    unsigned epoch = 0;

    for (int t = 0; t < Tlen; t++) {
        const float* hr_in  = g_hr + (size_t)(t & 1) * BHd;
        float*       hr_out = g_hr + (size_t)((t + 1) & 1) * BHd;

        // prefetch gate-phase input
        float4 xp = *(const float4*)&g_xproj[((size_t)(t * Bsz + gm)) * FourH
                                             + (c0 + ghc) * 4];

        float acc[4][4];
#pragma unroll
        for (int mt = 0; mt < 4; mt++)
#pragma unroll
            for (int r = 0; r < 4; r++) acc[mt][r] = 0.f;

        if (t > 0) {
            const float* hsrc = hr_in + srow * Hd + gs * 256 + shalf * 32;
            uint32_t dbase = sbase + (gs * RGSEG + srow * RGPITCH + shalf * 32) * 4;

            // issue it -> slot it%3
            auto issue = [&](int it) {
                uint32_t dst = dbase + ((it % 3) * SLOT_F) * 4;
#pragma unroll
                for (int j = 0; j < 8; j++)
                    cp16(dst + j * 16, hsrc + it * 64 + j * 4);
                cp_commit();
            };

            issue(0);
            issue(1);

#pragma unroll
            for (int it = 0; it < 4; it++) {
                cp_wait<1>();
                __syncthreads();
                if (it + 2 < 4) issue(it + 2); else cp_commit();

                uint32_t asb = sbase + ((it % 3) * SLOT_F + s * RGSEG) * 4;
#pragma unroll
                for (int kk = 0; kk < 8; kk++) {
                    int j = it * 8 + kk;
                    uint32_t addr = asb + (lm_row * RGPITCH + kk * 8 + lm_k) * 4;
#pragma unroll
                    for (int mt = 0; mt < 4; mt++) {
                        uint32_t a0, a1, a2, a3;
                        ldsm_x4(a0, a1, a2, a3, addr + (mt * 16 * RGPITCH) * 4);
                        mma_tf32(acc[mt], a0, a1, a2, a3, b0[j], b1[j]);
                    }
                }
            }
        }

        // write k-split partials into pD (per-warp-disjoint regions)
#pragma unroll
        for (int mt = 0; mt < 4; mt++) {
            int row = mt * 16 + (lane >> 2);
            float* p = pD + s * PDSEG + row * PDPITCH + g * 8 + 2 * (lane & 3);
            p[0] = acc[mt][0];
            p[1] = acc[mt][1];
            p[8 * PDPITCH]     = acc[mt][2];
            p[8 * PDPITCH + 1] = acc[mt][3];
        }
        __syncthreads();

        // fused gate phase (one (row, hcol) item per thread)
        {
            float zi = xp.x, zf = xp.y, zg = xp.z, zo = xp.w;
#pragma unroll
            for (int sp = 0; sp < 4; sp++) {
                const float* q = pD + sp * PDSEG + gm * PDPITCH;
                zi += q[ghc];
                zf += q[8 + ghc];
                zg += q[16 + ghc];
                zo += q[24 + ghc];
            }
            float si = sigmoid_f(zi);
            float sf = sigmoid_f(zf);
            float so = sigmoid_f(zo);
            float tg = tanh_f(zg);
            float cn = sf * creg + si * tg;
            float hn = so * tanh_f(cn);
            creg = cn;
            float hrnd = __uint_as_float(f2tf32(hn));
            hr_out[ghi] = hrnd;
            if (writeseq)
                seq[((size_t)(t * Bsz + gm)) * Hd + c0 + ghc] = hrnd;
            else if (t == Tlen - 1)
                g_hfull[ghi] = hn;   // last layer, last step: full precision
        }
        grid_sync(++epoch);
    }
}

// ---------------- head ----------------
__global__ void head_kernel(const float* __restrict__ Wc, const float* __restrict__ bc,
                            float* __restrict__ out)
{
    int b = blockIdx.x;
    int w = threadIdx.x >> 5;
    int lane = threadIdx.x & 31;
    const float* h = g_hfull + b * Hd;
    float s = 0.f;
    for (int k = lane; k < Hd; k += 32) s += h[k] * Wc[k * Cd + w];
#pragma unroll
    for (int o = 16; o > 0; o >>= 1) s += __shfl_down_sync(0xffffffffu, s, o);
    if (lane == 0) out[b * Cd + w] = s + bc[w];
}

// ---------------- launch ----------------
extern "C" void kernel_launch(void* const* d_in, const int* in_sizes, int n_in,
                              void* d_out, int out_size)
{
    const float* x    = (const float*)d_in[0];
    const float* Wx0  = (const float*)d_in[1];
    const float* Wxs  = (const float*)d_in[2];
    const float* Whs  = (const float*)d_in[3];
    const float* bs   = (const float*)d_in[4];
    const float* Wc   = (const float*)d_in[5];
    const float* bc   = (const float*)d_in[6];
    float* out = (float*)d_out;

    cudaFuncSetAttribute(proj_gemm_tc,
                         cudaFuncAttributeMaxDynamicSharedMemorySize, PROJ_SMEM);
    cudaFuncSetAttribute(lstm_layer_tc,
                         cudaFuncAttributeMaxDynamicSharedMemorySize, REC_SMEM);

    void* sync_addr = nullptr;
    cudaGetSymbolAddress(&sync_addr, g_sync);

    float* xtf = nullptr; float* wtf = nullptr;
    { void* p; cudaGetSymbolAddress(&p, g_xtf); xtf = (float*)p; }
    { void* p; cudaGetSymbolAddress(&p, g_wtf); wtf = (float*)p; }
    float* hs0 = nullptr; float* hs1 = nullptr;
    { void* p; cudaGetSymbolAddress(&p, g_hseq0); hs0 = (float*)p; }
    { void* p; cudaGetSymbolAddress(&p, g_hseq1); hs1 = (float*)p; }

    preround_x<<<512, 256>>>(x);
    // transpose + round input weights: Wx0 [128,4096] -> [4096,128]
    transpose_tf32<<<dim3(FourH / 32, Din / 32), dim3(32, 8)>>>(Wx0, wtf, Din, FourH);
    for (int l = 1; l < Ld; l++)
        transpose_tf32<<<dim3(FourH / 32, Hd / 32), dim3(32, 8)>>>(
            Wxs + (size_t)(l - 1) * Hd * FourH,
            wtf + (size_t)Din * FourH + (size_t)(l - 1) * Hd * FourH,
            Hd, FourH);

    dim3 pgrid(FourH / 256, Mrows / 128);   // 16 x 128

    for (int l = 0; l < Ld; l++) {
        const float* A  = (l == 0) ? xtf : (((l - 1) & 1) == 0 ? hs0 : hs1);
        const float* Wt = (l == 0) ? wtf : (wtf + (size_t)Din * FourH
                                               + (size_t)(l - 1) * Hd * FourH);
        int K  = (l == 0) ? Din : Hd;
        int st = (l == 0) ? Din : Bsz * Hd;
        int sb = (l == 0) ? Tlen * Din : Hd;

        proj_gemm_tc<<<pgrid, 512, PROJ_SMEM>>>(A, st, sb, K, Wt,
                                                bs + (size_t)l * FourH);

        cudaMemsetAsync(sync_addr, 0, 129 * 32 * sizeof(unsigned));

        const float* Wh = Whs + (size_t)l * Hd * FourH;
        lstm_layer_tc<<<128, 512, REC_SMEM>>>(Wh, l & 1, (l < Ld - 1) ? 1 : 0);
    }

    head_kernel<<<Bsz, 320>>>(Wc, bc, out);
}

// round 10
// speedup vs baseline: 1.4547x; 1.4547x over previous
#include <cuda_runtime.h>
#include <math.h>
#include <stdint.h>

#define Bsz   64
#define Tlen  256
#define Din   128
#define Hd    1024
#define Ld    5
#define Cd    10
#define FourH 4096
#define Mrows (Tlen * Bsz)   // 16384
#define BHd   (Bsz * Hd)

// ---------------- scratch (static device globals; no allocs) ----------------
// xproj layout is GATE-INTERLEAVED: xproj[row][hcol][gate], gate order i,f,g,o
__device__ float g_xproj[(size_t)Mrows * FourH];   // 256 MB
__device__ float g_hseq0[(size_t)Mrows * Hd];      // 64 MB (tf32-prerounded)
__device__ float g_hseq1[(size_t)Mrows * Hd];      // 64 MB (tf32-prerounded)
__device__ float g_h0[BHd];                        // full precision (head)
__device__ float g_h1[BHd];
__device__ float g_hr0[BHd];                       // tf32-prerounded (mma staging)
__device__ float g_hr1[BHd];
__device__ float g_c[BHd];
__device__ float g_xtf[(size_t)Bsz * Tlen * Din];          // prerounded x
__device__ float g_wtf[(size_t)(Din + 4 * Hd) * FourH];    // prerounded TRANSPOSED Wx0|Wxs
__device__ unsigned g_sync[128 * 32];   // per-block epoch flags (128B strided)

// ---------------- PTX helpers ----------------
__device__ __forceinline__ uint32_t f2tf32(float f) {
    uint32_t u; asm("cvt.rna.tf32.f32 %0, %1;" : "=r"(u) : "f"(f)); return u;
}
__device__ __forceinline__ void ldsm_x4(uint32_t& r0, uint32_t& r1, uint32_t& r2,
                                        uint32_t& r3, uint32_t addr) {
    asm volatile("ldmatrix.sync.aligned.m8n8.x4.shared.b16 {%0,%1,%2,%3}, [%4];"
                 : "=r"(r0), "=r"(r1), "=r"(r2), "=r"(r3) : "r"(addr));
}
__device__ __forceinline__ void mma_tf32(float* d, uint32_t a0, uint32_t a1,
                                         uint32_t a2, uint32_t a3,
                                         uint32_t b0, uint32_t b1) {
    asm volatile("mma.sync.aligned.m16n8k8.row.col.f32.tf32.tf32.f32 "
                 "{%0,%1,%2,%3}, {%4,%5,%6,%7}, {%8,%9}, {%0,%1,%2,%3};"
                 : "+f"(d[0]), "+f"(d[1]), "+f"(d[2]), "+f"(d[3])
                 : "r"(a0), "r"(a1), "r"(a2), "r"(a3), "r"(b0), "r"(b1));
}
__device__ __forceinline__ void cp16(uint32_t dst, const void* src) {
    asm volatile("cp.async.cg.shared.global [%0], [%1], 16;" :: "r"(dst), "l"(src));
}
__device__ __forceinline__ void cp_commit() {
    asm volatile("cp.async.commit_group;");
}
template <int N>
__device__ __forceinline__ void cp_wait() {
    asm volatile("cp.async.wait_group %0;" :: "n"(N));
}

// ---------------- grid barrier: all-to-all flag scan ----------------
__device__ __forceinline__ void grid_sync(unsigned epoch) {
    __syncthreads();
    if (threadIdx.x == 0) {
        __threadfence();
        asm volatile("st.release.gpu.global.u32 [%0], %1;"
                     :: "l"(&g_sync[blockIdx.x * 32]), "r"(epoch) : "memory");
    }
    if (threadIdx.x < 128) {
        unsigned v;
        do {
            asm volatile("ld.acquire.gpu.global.u32 %0, [%1];"
                         : "=r"(v) : "l"(&g_sync[threadIdx.x * 32]) : "memory");
        } while (v < epoch);
    }
    __syncthreads();
}

// ---------------- fast activations ----------------
__device__ __forceinline__ float sigmoid_f(float x) {
    return __fdividef(1.f, 1.f + __expf(-x));
}
__device__ __forceinline__ float tanh_f(float x) {
    float e = __expf(2.f * x);
    return 1.f - __fdividef(2.f, e + 1.f);
}

// ---------------- preround x ----------------
__global__ void preround_x(const float* __restrict__ x) {
    size_t nx = (size_t)Bsz * Tlen * Din;
    size_t stride = (size_t)gridDim.x * blockDim.x;
    for (size_t i = (size_t)blockIdx.x * blockDim.x + threadIdx.x; i < nx; i += stride)
        g_xtf[i] = __uint_as_float(f2tf32(x[i]));
}

// ---------------- tiled transpose + tf32 round: src[K][N] -> dst[N][K] ------
__global__ void transpose_tf32(const float* __restrict__ src, float* __restrict__ dst,
                               int K, int N) {
    __shared__ float tile[32][33];
    int kb = blockIdx.y * 32, nb = blockIdx.x * 32;
    int tx = threadIdx.x, ty = threadIdx.y;   // 32 x 8
    for (int i = ty; i < 32; i += 8)
        tile[i][tx] = src[(size_t)(kb + i) * N + nb + tx];
    __syncthreads();
    for (int i = ty; i < 32; i += 8)
        dst[(size_t)(nb + i) * K + kb + tx] = __uint_as_float(f2tf32(tile[tx][i]));
}

// ============================================================================
// Input projection GEMM (tf32, cp.async 3-stage pipeline, ldmatrix A and B)
//   Block tile 128(M) x 256(N), k-tile 32, 512 threads = 16 warps (2m x 8n).
//   W is pre-transposed n-major: Wt[n][k].
// ============================================================================
#define PBP 36
#define STG_F (128 * 32 + 256 * PBP)       // 13312 floats per stage
#define PROJ_SMEM (3 * STG_F * 4)          // 159744 B

__global__ __launch_bounds__(512) void proj_gemm_tc(
    const float* __restrict__ A, int stride_t, int stride_b, int K,
    const float* __restrict__ Wt, const float* __restrict__ bias)
{
    extern __shared__ float ps[];
    uint32_t sbase = (uint32_t)__cvta_generic_to_shared(ps);

    int tid  = threadIdx.x;
    int wid  = tid >> 5;
    int lane = tid & 31;
    int row0 = blockIdx.y * 128;
    int col0 = blockIdx.x * 256;

    int wm = wid & 1;          // m-group (64 rows)
    int wn = wid >> 1;         // n-group (32 cols)

    // A issue mapping
    int a_row = tid >> 2;
    int a_c2  = (tid & 3) * 2;
    int agrow = row0 + a_row;
    const float* Aptr = A + (size_t)(agrow >> 6) * stride_t
                          + (size_t)(agrow & 63) * stride_b;
    int a_sw0 = a_row * 32 + ((a_c2)     ^ (a_row & 7)) * 4;
    int a_sw1 = a_row * 32 + ((a_c2 + 1) ^ (a_row & 7)) * 4;

    // ldmatrix lane components (A)
    int lm_row = (lane & 7) + ((lane >> 3) & 1) * 8;
    int lm_cs  = lane >> 4;
    int lm_x   = lane & 7;

    // ldmatrix lane components (B): matrix idx m = lane>>3
    int b_m   = lane >> 3;          // 0..3
    int b_nt4 = b_m >> 1;           // sub n-tile within pair
    int b_kc  = b_m & 1;            // k chunk (0 or +4)
    int b_r   = lane & 7;           // row within 8

    float acc[4][4][4];
#pragma unroll
    for (int i = 0; i < 4; i++)
#pragma unroll
        for (int j = 0; j < 4; j++)
#pragma unroll
            for (int r = 0; r < 4; r++) acc[i][j][r] = 0.f;

    int ntiles = K >> 5;

    auto issue = [&](int stage, int kt) {
        if (kt < ntiles) {
            int kb = kt * 32;
            uint32_t as = sbase + (stage * STG_F) * 4;
            cp16(as + a_sw0 * 4, Aptr + kb + a_c2 * 4);
            cp16(as + a_sw1 * 4, Aptr + kb + (a_c2 + 1) * 4);
            uint32_t bsm = sbase + (stage * STG_F + 128 * 32) * 4;
#pragma unroll
            for (int i = 0; i < 4; i++) {
                int id = i * 512 + tid;
                int n = id >> 3, k4 = (id & 7) * 4;
                cp16(bsm + (n * PBP + k4) * 4,
                     Wt + (size_t)(col0 + n) * K + kb + k4);
            }
        }
        cp_commit();
    };

    issue(0, 0);
    issue(1, 1);

    for (int kt = 0; kt < ntiles; kt++) {
        cp_wait<1>();
        __syncthreads();
        int cur = kt % 3;
        issue((kt + 2) % 3, kt + 2);

        uint32_t asb = sbase + (cur * STG_F) * 4;
        uint32_t bsb = sbase + (cur * STG_F + 128 * 32) * 4;

#pragma unroll
        for (int kk = 0; kk < 4; kk++) {
            uint32_t bf[4][2];
#pragma unroll
            for (int np = 0; np < 2; np++) {
                int nrow = wn * 32 + (np * 2 + b_nt4) * 8 + b_r;
                uint32_t addr = bsb + (nrow * PBP + kk * 8 + b_kc * 4) * 4;
                ldsm_x4(bf[np * 2][0], bf[np * 2][1],
                        bf[np * 2 + 1][0], bf[np * 2 + 1][1], addr);
            }
#pragma unroll
            for (int mt = 0; mt < 4; mt++) {
                int arow = wm * 64 + mt * 16 + lm_row;
                int phys = (kk * 2 + lm_cs) ^ lm_x;
                uint32_t a0, a1, a2, a3;
                ldsm_x4(a0, a1, a2, a3, asb + (arow * 32 + phys * 4) * 4);
#pragma unroll
                for (int nt = 0; nt < 4; nt++)
                    mma_tf32(acc[mt][nt], a0, a1, a2, a3, bf[nt][0], bf[nt][1]);
            }
        }
    }

    // epilogue: add bias, store gate-interleaved
    int gate  = col0 >> 10;
    int hbase = col0 & 1023;
#pragma unroll
    for (int mt = 0; mt < 4; mt++) {
        int row = row0 + wm * 64 + mt * 16 + (lane >> 2);
#pragma unroll
        for (int nt = 0; nt < 4; nt++) {
            int nl = wn * 32 + nt * 8 + 2 * (lane & 3);
            float b0v = bias[col0 + nl];
            float b1v = bias[col0 + nl + 1];
            int hcol = hbase + nl;
            float* o0 = g_xproj + (size_t)row * FourH + hcol * 4 + gate;
            o0[0] = acc[mt][nt][0] + b0v;
            o0[4] = acc[mt][nt][1] + b1v;
            float* o1 = o0 + (size_t)8 * FourH;
            o1[0] = acc[mt][nt][2] + b0v;
            o1[4] = acc[mt][nt][3] + b1v;
        }
    }
}

// ============================================================================
// Persistent recurrent layer (R6 config, verbatim except barrier impl)
//   128 blocks x 512 threads; 16 warps = (gate g = wid&3) x (k-split s = wid>>2)
//   h staged from PREROUNDED hr buffers via 3-stage cp.async ring, k-tile 32.
// ============================================================================
#define RPITCH 36
#define RSEG   (64 * RPITCH)            // 2304 floats per k-split segment
#define KTF    (4 * RSEG)               // 9216 floats per staged k-tile
#define NSTG   3
#define REC_SMEM ((NSTG * KTF + 4 * RSEG) * 4)   // 147456 B

__global__ __launch_bounds__(512) void lstm_layer_tc(
    const float* __restrict__ Wh, int seqsel, int writeseq)
{
    extern __shared__ float rs[];
    float* pD = rs + NSTG * KTF;
    uint32_t sbase = (uint32_t)__cvta_generic_to_shared(rs);

    int tid  = threadIdx.x;
    int wid  = tid >> 5;
    int lane = tid & 31;
    int g    = wid & 3;
    int s    = wid >> 2;
    int c0   = blockIdx.x * 8;

    // ---- Wh slice into registers as tf32 B-fragments ----
    uint32_t b0[32], b1[32];
    {
        const float* Wb = Wh + (size_t)(s * 256) * FourH + g * Hd + c0 + (lane >> 2);
#pragma unroll
        for (int j = 0; j < 32; j++) {
            int k = j * 8 + (lane & 3);
            b0[j] = f2tf32(Wb[(size_t)k * FourH]);
            b1[j] = f2tf32(Wb[(size_t)(k + 4) * FourH]);
        }
    }

    // ---- zero own state columns ----
    {
        int m = tid >> 3, hc = tid & 7;
        int hi = m * Hd + c0 + hc;
        g_c[hi] = 0.f; g_h0[hi] = 0.f; g_h1[hi] = 0.f;
        g_hr0[hi] = 0.f; g_hr1[hi] = 0.f;
    }
    unsigned epoch = 0;
    grid_sync(++epoch);

    float* seq = seqsel ? g_hseq1 : g_hseq0;

    int srow = wid * 4 + (lane >> 3);    // staged row 0..63
    int sk4  = (lane & 7) * 4;           // k offset within tile
    int lm_row = (lane & 7) + ((lane >> 3) & 1) * 8;
    int lm_k   = (lane >> 4) * 4;
    int gm = tid >> 3, ghc = tid & 7;
    int ghi = gm * Hd + c0 + ghc;

    for (int t = 0; t < Tlen; t++) {
        const float* hr_in  = (t & 1) ? g_hr1 : g_hr0;
        float*       h_out  = (t & 1) ? g_h0 : g_h1;
        float*       hr_out = (t & 1) ? g_hr0 : g_hr1;

        // prefetch gate-phase inputs (independent of staging)
        float4 xp = *(const float4*)&g_xproj[((size_t)(t * Bsz + gm)) * FourH
                                             + (c0 + ghc) * 4];
        float cold = g_c[ghi];

        const float* hsrc = hr_in + srow * Hd + sk4;

        // 3-stage cp.async ring over 8 k-tiles
#pragma unroll
        for (int p = 0; p < 2; p++) {
            uint32_t dst = sbase + ((p % NSTG) * KTF + srow * RPITCH + sk4) * 4;
#pragma unroll
            for (int sp = 0; sp < 4; sp++)
                cp16(dst + sp * RSEG * 4, hsrc + sp * 256 + p * 32);
            cp_commit();
        }

        float acc[4][4];
#pragma unroll
        for (int mt = 0; mt < 4; mt++)
#pragma unroll
            for (int r = 0; r < 4; r++) acc[mt][r] = 0.f;

#pragma unroll
        for (int kt = 0; kt < 8; kt++) {
            cp_wait<1>();
            __syncthreads();
            // issue kt+2
            if (kt + 2 < 8) {
                uint32_t dst = sbase + (((kt + 2) % NSTG) * KTF
                                        + srow * RPITCH + sk4) * 4;
#pragma unroll
                for (int sp = 0; sp < 4; sp++)
                    cp16(dst + sp * RSEG * 4, hsrc + sp * 256 + (kt + 2) * 32);
            }
            cp_commit();

            uint32_t asb = sbase + ((kt % NSTG) * KTF) * 4;
#pragma unroll
            for (int kk = 0; kk < 4; kk++) {
                int j = kt * 4 + kk;
                uint32_t addr = asb +
                    (s * RSEG + lm_row * RPITCH + kk * 8 + lm_k) * 4;
#pragma unroll
                for (int mt = 0; mt < 4; mt++) {
                    uint32_t a0, a1, a2, a3;
                    ldsm_x4(a0, a1, a2, a3, addr + (mt * 16 * RPITCH) * 4);
                    mma_tf32(acc[mt], a0, a1, a2, a3, b0[j], b1[j]);
                }
            }
        }

        // write k-split partials (per-warp private region)
#pragma unroll
        for (int mt = 0; mt < 4; mt++) {
            int row = mt * 16 + (lane >> 2);
            float* p = pD + s * RSEG + row * RPITCH + g * 8 + 2 * (lane & 3);
            p[0] = acc[mt][0];
            p[1] = acc[mt][1];
            p[8 * RPITCH]     = acc[mt][2];
            p[8 * RPITCH + 1] = acc[mt][3];
        }
        __syncthreads();

        // fused gate phase
        {
            float zi = xp.x, zf = xp.y, zg = xp.z, zo = xp.w;
#pragma unroll
            for (int sp = 0; sp < 4; sp++) {
                const float* q = pD + sp * RSEG + gm * RPITCH;
                zi += q[ghc];
                zf += q[8 + ghc];
                zg += q[16 + ghc];
                zo += q[24 + ghc];
            }
            float si = sigmoid_f(zi);
            float sf = sigmoid_f(zf);
            float so = sigmoid_f(zo);
            float tg = tanh_f(zg);
            float cn = sf * cold + si * tg;
            float hn = so * tanh_f(cn);
            g_c[ghi]    = cn;
            h_out[ghi]  = hn;
            float hrnd  = __uint_as_float(f2tf32(hn));
            hr_out[ghi] = hrnd;
            if (writeseq)
                seq[((size_t)(t * Bsz + gm)) * Hd + c0 + ghc] = hrnd;
        }
        grid_sync(++epoch);
    }
}

// ---------------- head ----------------
__global__ void head_kernel(const float* __restrict__ Wc, const float* __restrict__ bc,
                            float* __restrict__ out)
{
    int b = blockIdx.x;
    int w = threadIdx.x >> 5;
    int lane = threadIdx.x & 31;
    const float* h = g_h0 + b * Hd;   // t=255 (odd) writes buffer 0
    float s = 0.f;
    for (int k = lane; k < Hd; k += 32) s += h[k] * Wc[k * Cd + w];
#pragma unroll
    for (int o = 16; o > 0; o >>= 1) s += __shfl_down_sync(0xffffffffu, s, o);
    if (lane == 0) out[b * Cd + w] = s + bc[w];
}

// ---------------- launch ----------------
extern "C" void kernel_launch(void* const* d_in, const int* in_sizes, int n_in,
                              void* d_out, int out_size)
{
    const float* x    = (const float*)d_in[0];
    const float* Wx0  = (const float*)d_in[1];
    const float* Wxs  = (const float*)d_in[2];
    const float* Whs  = (const float*)d_in[3];
    const float* bs   = (const float*)d_in[4];
    const float* Wc   = (const float*)d_in[5];
    const float* bc   = (const float*)d_in[6];
    float* out = (float*)d_out;

    cudaFuncSetAttribute(proj_gemm_tc,
                         cudaFuncAttributeMaxDynamicSharedMemorySize, PROJ_SMEM);
    cudaFuncSetAttribute(lstm_layer_tc,
                         cudaFuncAttributeMaxDynamicSharedMemorySize, REC_SMEM);

    void* sync_addr = nullptr;
    cudaGetSymbolAddress(&sync_addr, g_sync);

    float* xtf = nullptr; float* wtf = nullptr;
    { void* p; cudaGetSymbolAddress(&p, g_xtf); xtf = (float*)p; }
    { void* p; cudaGetSymbolAddress(&p, g_wtf); wtf = (float*)p; }
    float* hs0 = nullptr; float* hs1 = nullptr;
    { void* p; cudaGetSymbolAddress(&p, g_hseq0); hs0 = (float*)p; }
    { void* p; cudaGetSymbolAddress(&p, g_hseq1); hs1 = (float*)p; }

    preround_x<<<512, 256>>>(x);
    // transpose + round input weights: Wx0 [128,4096] -> [4096,128]
    transpose_tf32<<<dim3(FourH / 32, Din / 32), dim3(32, 8)>>>(Wx0, wtf, Din, FourH);
    for (int l = 1; l < Ld; l++)
        transpose_tf32<<<dim3(FourH / 32, Hd / 32), dim3(32, 8)>>>(
            Wxs + (size_t)(l - 1) * Hd * FourH,
            wtf + (size_t)Din * FourH + (size_t)(l - 1) * Hd * FourH,
            Hd, FourH);

    dim3 pgrid(FourH / 256, Mrows / 128);   // 16 x 128

    for (int l = 0; l < Ld; l++) {
        const float* A  = (l == 0) ? xtf : (((l - 1) & 1) == 0 ? hs0 : hs1);
        const float* Wt = (l == 0) ? wtf : (wtf + (size_t)Din * FourH
                                               + (size_t)(l - 1) * Hd * FourH);
        int K  = (l == 0) ? Din : Hd;
        int st = (l == 0) ? Din : Bsz * Hd;
        int sb = (l == 0) ? Tlen * Din : Hd;

        proj_gemm_tc<<<pgrid, 512, PROJ_SMEM>>>(A, st, sb, K, Wt,
                                                bs + (size_t)l * FourH);

        cudaMemsetAsync(sync_addr, 0, 128 * 32 * sizeof(unsigned));

        const float* Wh = Whs + (size_t)l * Hd * FourH;
        lstm_layer_tc<<<128, 512, REC_SMEM>>>(Wh, l & 1, (l < Ld - 1) ? 1 : 0);
    }

    head_kernel<<<Bsz, 320>>>(Wc, bc, out);
}

// round 11
// speedup vs baseline: 1.4668x; 1.0083x over previous
#include <cuda_runtime.h>
#include <math.h>
#include <stdint.h>

#define Bsz   64
#define Tlen  256
#define Din   128
#define Hd    1024
#define Ld    5
#define Cd    10
#define FourH 4096
#define Mrows (Tlen * Bsz)   // 16384
#define BHd   (Bsz * Hd)

// ---------------- scratch (static device globals; no allocs) ----------------
// xproj layout is GATE-INTERLEAVED: xproj[row][hcol][gate], gate order i,f,g,o
__device__ float g_xproj[(size_t)Mrows * FourH];   // 256 MB
__device__ float g_hseq0[(size_t)Mrows * Hd];      // 64 MB (tf32-prerounded)
__device__ float g_hseq1[(size_t)Mrows * Hd];      // 64 MB (tf32-prerounded)
__device__ float g_h0[BHd];                        // full precision (head)
__device__ float g_h1[BHd];
__device__ float g_hr0[BHd];                       // tf32-prerounded (mma staging)
__device__ float g_hr1[BHd];
__device__ float g_c[BHd];
__device__ float g_xtf[(size_t)Bsz * Tlen * Din];          // prerounded x
__device__ float g_wtf[(size_t)(Din + 4 * Hd) * FourH];    // prerounded TRANSPOSED Wx0|Wxs
__device__ unsigned g_sync[128 * 32];   // per-block epoch flags (128B strided)

// ---------------- PTX helpers ----------------
__device__ __forceinline__ uint32_t f2tf32(float f) {
    uint32_t u; asm("cvt.rna.tf32.f32 %0, %1;" : "=r"(u) : "f"(f)); return u;
}
__device__ __forceinline__ void ldsm_x4(uint32_t& r0, uint32_t& r1, uint32_t& r2,
                                        uint32_t& r3, uint32_t addr) {
    asm volatile("ldmatrix.sync.aligned.m8n8.x4.shared.b16 {%0,%1,%2,%3}, [%4];"
                 : "=r"(r0), "=r"(r1), "=r"(r2), "=r"(r3) : "r"(addr));
}
__device__ __forceinline__ void mma_tf32(float* d, uint32_t a0, uint32_t a1,
                                         uint32_t a2, uint32_t a3,
                                         uint32_t b0, uint32_t b1) {
    asm volatile("mma.sync.aligned.m16n8k8.row.col.f32.tf32.tf32.f32 "
                 "{%0,%1,%2,%3}, {%4,%5,%6,%7}, {%8,%9}, {%0,%1,%2,%3};"
                 : "+f"(d[0]), "+f"(d[1]), "+f"(d[2]), "+f"(d[3])
                 : "r"(a0), "r"(a1), "r"(a2), "r"(a3), "r"(b0), "r"(b1));
}
__device__ __forceinline__ void cp16(uint32_t dst, const void* src) {
    asm volatile("cp.async.cg.shared.global [%0], [%1], 16;" :: "r"(dst), "l"(src));
}
__device__ __forceinline__ void cp_commit() {
    asm volatile("cp.async.commit_group;");
}
template <int N>
__device__ __forceinline__ void cp_wait() {
    asm volatile("cp.async.wait_group %0;" :: "n"(N));
}

// ---------------- grid barrier: all-to-all flag scan ----------------
__device__ __forceinline__ void grid_sync(unsigned epoch) {
    __syncthreads();
    if (threadIdx.x == 0) {
        __threadfence();
        asm volatile("st.release.gpu.global.u32 [%0], %1;"
                     :: "l"(&g_sync[blockIdx.x * 32]), "r"(epoch) : "memory");
    }
    if (threadIdx.x < 128) {
        unsigned v;
        do {
            asm volatile("ld.acquire.gpu.global.u32 %0, [%1];"
                         : "=r"(v) : "l"(&g_sync[threadIdx.x * 32]) : "memory");
        } while (v < epoch);
    }
    __syncthreads();
}

// ---------------- fast activations ----------------
__device__ __forceinline__ float sigmoid_f(float x) {
    return __fdividef(1.f, 1.f + __expf(-x));
}
__device__ __forceinline__ float tanh_f(float x) {
    float e = __expf(2.f * x);
    return 1.f - __fdividef(2.f, e + 1.f);
}

// ---------------- preround x ----------------
__global__ void preround_x(const float* __restrict__ x) {
    size_t nx = (size_t)Bsz * Tlen * Din;
    size_t stride = (size_t)gridDim.x * blockDim.x;
    for (size_t i = (size_t)blockIdx.x * blockDim.x + threadIdx.x; i < nx; i += stride)
        g_xtf[i] = __uint_as_float(f2tf32(x[i]));
}

// ---------------- tiled transpose + tf32 round: src[K][N] -> dst[N][K] ------
__global__ void transpose_tf32(const float* __restrict__ src, float* __restrict__ dst,
                               int K, int N) {
    __shared__ float tile[32][33];
    int kb = blockIdx.y * 32, nb = blockIdx.x * 32;
    int tx = threadIdx.x, ty = threadIdx.y;   // 32 x 8
    for (int i = ty; i < 32; i += 8)
        tile[i][tx] = src[(size_t)(kb + i) * N + nb + tx];
    __syncthreads();
    for (int i = ty; i < 32; i += 8)
        dst[(size_t)(nb + i) * K + kb + tx] = __uint_as_float(f2tf32(tile[tx][i]));
}

// ============================================================================
// Input projection GEMM (tf32, cp.async 3-stage pipeline, ldmatrix A and B)
//   Block tile 128(M) x 256(N), k-tile 32, 512 threads = 16 warps (2m x 8n).
//   W is pre-transposed n-major: Wt[n][k].
// ============================================================================
#define PBP 36
#define STG_F (128 * 32 + 256 * PBP)       // 13312 floats per stage
#define PROJ_SMEM (3 * STG_F * 4)          // 159744 B

__global__ __launch_bounds__(512) void proj_gemm_tc(
    const float* __restrict__ A, int stride_t, int stride_b, int K,
    const float* __restrict__ Wt, const float* __restrict__ bias)
{
    extern __shared__ float ps[];
    uint32_t sbase = (uint32_t)__cvta_generic_to_shared(ps);

    int tid  = threadIdx.x;
    int wid  = tid >> 5;
    int lane = tid & 31;
    int row0 = blockIdx.y * 128;
    int col0 = blockIdx.x * 256;

    int wm = wid & 1;          // m-group (64 rows)
    int wn = wid >> 1;         // n-group (32 cols)

    // A issue mapping
    int a_row = tid >> 2;
    int a_c2  = (tid & 3) * 2;
    int agrow = row0 + a_row;
    const float* Aptr = A + (size_t)(agrow >> 6) * stride_t
                          + (size_t)(agrow & 63) * stride_b;
    int a_sw0 = a_row * 32 + ((a_c2)     ^ (a_row & 7)) * 4;
    int a_sw1 = a_row * 32 + ((a_c2 + 1) ^ (a_row & 7)) * 4;

    // ldmatrix lane components (A)
    int lm_row = (lane & 7) + ((lane >> 3) & 1) * 8;
    int lm_cs  = lane >> 4;
    int lm_x   = lane & 7;

    // ldmatrix lane components (B): matrix idx m = lane>>3
    int b_m   = lane >> 3;          // 0..3
    int b_nt4 = b_m >> 1;           // sub n-tile within pair
    int b_kc  = b_m & 1;            // k chunk (0 or +4)
    int b_r   = lane & 7;           // row within 8

    float acc[4][4][4];
#pragma unroll
    for (int i = 0; i < 4; i++)
#pragma unroll
        for (int j = 0; j < 4; j++)
#pragma unroll
            for (int r = 0; r < 4; r++) acc[i][j][r] = 0.f;

    int ntiles = K >> 5;

    auto issue = [&](int stage, int kt) {
        if (kt < ntiles) {
            int kb = kt * 32;
            uint32_t as = sbase + (stage * STG_F) * 4;
            cp16(as + a_sw0 * 4, Aptr + kb + a_c2 * 4);
            cp16(as + a_sw1 * 4, Aptr + kb + (a_c2 + 1) * 4);
            uint32_t bsm = sbase + (stage * STG_F + 128 * 32) * 4;
#pragma unroll
            for (int i = 0; i < 4; i++) {
                int id = i * 512 + tid;
                int n = id >> 3, k4 = (id & 7) * 4;
                cp16(bsm + (n * PBP + k4) * 4,
                     Wt + (size_t)(col0 + n) * K + kb + k4);
            }
        }
        cp_commit();
    };

    issue(0, 0);
    issue(1, 1);

    for (int kt = 0; kt < ntiles; kt++) {
        cp_wait<1>();
        __syncthreads();
        int cur = kt % 3;
        issue((kt + 2) % 3, kt + 2);

        uint32_t asb = sbase + (cur * STG_F) * 4;
        uint32_t bsb = sbase + (cur * STG_F + 128 * 32) * 4;

#pragma unroll
        for (int kk = 0; kk < 4; kk++) {
            uint32_t bf[4][2];
#pragma unroll
            for (int np = 0; np < 2; np++) {
                int nrow = wn * 32 + (np * 2 + b_nt4) * 8 + b_r;
                uint32_t addr = bsb + (nrow * PBP + kk * 8 + b_kc * 4) * 4;
                ldsm_x4(bf[np * 2][0], bf[np * 2][1],
                        bf[np * 2 + 1][0], bf[np * 2 + 1][1], addr);
            }
#pragma unroll
            for (int mt = 0; mt < 4; mt++) {
                int arow = wm * 64 + mt * 16 + lm_row;
                int phys = (kk * 2 + lm_cs) ^ lm_x;
                uint32_t a0, a1, a2, a3;
                ldsm_x4(a0, a1, a2, a3, asb + (arow * 32 + phys * 4) * 4);
#pragma unroll
                for (int nt = 0; nt < 4; nt++)
                    mma_tf32(acc[mt][nt], a0, a1, a2, a3, bf[nt][0], bf[nt][1]);
            }
        }
    }

    // epilogue: add bias, store gate-interleaved
    int gate  = col0 >> 10;
    int hbase = col0 & 1023;
#pragma unroll
    for (int mt = 0; mt < 4; mt++) {
        int row = row0 + wm * 64 + mt * 16 + (lane >> 2);
#pragma unroll
        for (int nt = 0; nt < 4; nt++) {
            int nl = wn * 32 + nt * 8 + 2 * (lane & 3);
            float b0v = bias[col0 + nl];
            float b1v = bias[col0 + nl + 1];
            int hcol = hbase + nl;
            float* o0 = g_xproj + (size_t)row * FourH + hcol * 4 + gate;
            o0[0] = acc[mt][nt][0] + b0v;
            o0[4] = acc[mt][nt][1] + b1v;
            float* o1 = o0 + (size_t)8 * FourH;
            o1[0] = acc[mt][nt][2] + b0v;
            o1[4] = acc[mt][nt][3] + b1v;
        }
    }
}

// ============================================================================
// Persistent recurrent layer (R10 config; ONLY change: 4-stage ring,
//   3-tile lookahead, cp.async wait_group<2>)
//   128 blocks x 512 threads; 16 warps = (gate g = wid&3) x (k-split s = wid>>2)
// ============================================================================
#define RPITCH 36
#define RSEG   (64 * RPITCH)            // 2304 floats per k-split segment
#define KTF    (4 * RSEG)               // 9216 floats per staged k-tile
#define NSTG   4
#define REC_SMEM ((NSTG * KTF + 4 * RSEG) * 4)   // 184320 B

__global__ __launch_bounds__(512) void lstm_layer_tc(
    const float* __restrict__ Wh, int seqsel, int writeseq)
{
    extern __shared__ float rs[];
    float* pD = rs + NSTG * KTF;
    uint32_t sbase = (uint32_t)__cvta_generic_to_shared(rs);

    int tid  = threadIdx.x;
    int wid  = tid >> 5;
    int lane = tid & 31;
    int g    = wid & 3;
    int s    = wid >> 2;
    int c0   = blockIdx.x * 8;

    // ---- Wh slice into registers as tf32 B-fragments ----
    uint32_t b0[32], b1[32];
    {
        const float* Wb = Wh + (size_t)(s * 256) * FourH + g * Hd + c0 + (lane >> 2);
#pragma unroll
        for (int j = 0; j < 32; j++) {
            int k = j * 8 + (lane & 3);
            b0[j] = f2tf32(Wb[(size_t)k * FourH]);
            b1[j] = f2tf32(Wb[(size_t)(k + 4) * FourH]);
        }
    }

    // ---- zero own state columns ----
    {
        int m = tid >> 3, hc = tid & 7;
        int hi = m * Hd + c0 + hc;
        g_c[hi] = 0.f; g_h0[hi] = 0.f; g_h1[hi] = 0.f;
        g_hr0[hi] = 0.f; g_hr1[hi] = 0.f;
    }
    unsigned epoch = 0;
    grid_sync(++epoch);

    float* seq = seqsel ? g_hseq1 : g_hseq0;

    int srow = wid * 4 + (lane >> 3);    // staged row 0..63
    int sk4  = (lane & 7) * 4;           // k offset within tile
    int lm_row = (lane & 7) + ((lane >> 3) & 1) * 8;
    int lm_k   = (lane >> 4) * 4;
    int gm = tid >> 3, ghc = tid & 7;
    int ghi = gm * Hd + c0 + ghc;

    for (int t = 0; t < Tlen; t++) {
        const float* hr_in  = (t & 1) ? g_hr1 : g_hr0;
        float*       h_out  = (t & 1) ? g_h0 : g_h1;
        float*       hr_out = (t & 1) ? g_hr0 : g_hr1;

        // prefetch gate-phase inputs (independent of staging)
        float4 xp = *(const float4*)&g_xproj[((size_t)(t * Bsz + gm)) * FourH
                                             + (c0 + ghc) * 4];
        float cold = g_c[ghi];

        const float* hsrc = hr_in + srow * Hd + sk4;

        // 4-stage cp.async ring over 8 k-tiles, 3-tile lookahead
#pragma unroll
        for (int p = 0; p < 3; p++) {
            uint32_t dst = sbase + ((p % NSTG) * KTF + srow * RPITCH + sk4) * 4;
#pragma unroll
            for (int sp = 0; sp < 4; sp++)
                cp16(dst + sp * RSEG * 4, hsrc + sp * 256 + p * 32);
            cp_commit();
        }

        float acc[4][4];
#pragma unroll
        for (int mt = 0; mt < 4; mt++)
#pragma unroll
            for (int r = 0; r < 4; r++) acc[mt][r] = 0.f;

#pragma unroll
        for (int kt = 0; kt < 8; kt++) {
            cp_wait<2>();
            __syncthreads();
            // issue kt+3
            if (kt + 3 < 8) {
                uint32_t dst = sbase + (((kt + 3) % NSTG) * KTF
                                        + srow * RPITCH + sk4) * 4;
#pragma unroll
                for (int sp = 0; sp < 4; sp++)
                    cp16(dst + sp * RSEG * 4, hsrc + sp * 256 + (kt + 3) * 32);
            }
            cp_commit();

            uint32_t asb = sbase + ((kt % NSTG) * KTF) * 4;
#pragma unroll
            for (int kk = 0; kk < 4; kk++) {
                int j = kt * 4 + kk;
                uint32_t addr = asb +
                    (s * RSEG + lm_row * RPITCH + kk * 8 + lm_k) * 4;
#pragma unroll
                for (int mt = 0; mt < 4; mt++) {
                    uint32_t a0, a1, a2, a3;
                    ldsm_x4(a0, a1, a2, a3, addr + (mt * 16 * RPITCH) * 4);
                    mma_tf32(acc[mt], a0, a1, a2, a3, b0[j], b1[j]);
                }
            }
        }

        // write k-split partials (per-warp private region)
#pragma unroll
        for (int mt = 0; mt < 4; mt++) {
            int row = mt * 16 + (lane >> 2);
            float* p = pD + s * RSEG + row * RPITCH + g * 8 + 2 * (lane & 3);
            p[0] = acc[mt][0];
            p[1] = acc[mt][1];
            p[8 * RPITCH]     = acc[mt][2];
            p[8 * RPITCH + 1] = acc[mt][3];
        }
        __syncthreads();

        // fused gate phase
        {
            float zi = xp.x, zf = xp.y, zg = xp.z, zo = xp.w;
#pragma unroll
            for (int sp = 0; sp < 4; sp++) {
                const float* q = pD + sp * RSEG + gm * RPITCH;
                zi += q[ghc];
                zf += q[8 + ghc];
                zg += q[16 + ghc];
                zo += q[24 + ghc];
            }
            float si = sigmoid_f(zi);
            float sf = sigmoid_f(zf);
            float so = sigmoid_f(zo);
            float tg = tanh_f(zg);
            float cn = sf * cold + si * tg;
            float hn = so * tanh_f(cn);
            g_c[ghi]    = cn;
            h_out[ghi]  = hn;
            float hrnd  = __uint_as_float(f2tf32(hn));
            hr_out[ghi] = hrnd;
            if (writeseq)
                seq[((size_t)(t * Bsz + gm)) * Hd + c0 + ghc] = hrnd;
        }
        grid_sync(++epoch);
    }
}

// ---------------- head ----------------
__global__ void head_kernel(const float* __restrict__ Wc, const float* __restrict__ bc,
                            float* __restrict__ out)
{
    int b = blockIdx.x;
    int w = threadIdx.x >> 5;
    int lane = threadIdx.x & 31;
    const float* h = g_h0 + b * Hd;   // t=255 (odd) writes buffer 0
    float s = 0.f;
    for (int k = lane; k < Hd; k += 32) s += h[k] * Wc[k * Cd + w];
#pragma unroll
    for (int o = 16; o > 0; o >>= 1) s += __shfl_down_sync(0xffffffffu, s, o);
    if (lane == 0) out[b * Cd + w] = s + bc[w];
}

// ---------------- launch ----------------
extern "C" void kernel_launch(void* const* d_in, const int* in_sizes, int n_in,
                              void* d_out, int out_size)
{
    const float* x    = (const float*)d_in[0];
    const float* Wx0  = (const float*)d_in[1];
    const float* Wxs  = (const float*)d_in[2];
    const float* Whs  = (const float*)d_in[3];
    const float* bs   = (const float*)d_in[4];
    const float* Wc   = (const float*)d_in[5];
    const float* bc   = (const float*)d_in[6];
    float* out = (float*)d_out;

    cudaFuncSetAttribute(proj_gemm_tc,
                         cudaFuncAttributeMaxDynamicSharedMemorySize, PROJ_SMEM);
    cudaFuncSetAttribute(lstm_layer_tc,
                         cudaFuncAttributeMaxDynamicSharedMemorySize, REC_SMEM);

    void* sync_addr = nullptr;
    cudaGetSymbolAddress(&sync_addr, g_sync);

    float* xtf = nullptr; float* wtf = nullptr;
    { void* p; cudaGetSymbolAddress(&p, g_xtf); xtf = (float*)p; }
    { void* p; cudaGetSymbolAddress(&p, g_wtf); wtf = (float*)p; }
    float* hs0 = nullptr; float* hs1 = nullptr;
    { void* p; cudaGetSymbolAddress(&p, g_hseq0); hs0 = (float*)p; }
    { void* p; cudaGetSymbolAddress(&p, g_hseq1); hs1 = (float*)p; }

    preround_x<<<512, 256>>>(x);
    // transpose + round input weights: Wx0 [128,4096] -> [4096,128]
    transpose_tf32<<<dim3(FourH / 32, Din / 32), dim3(32, 8)>>>(Wx0, wtf, Din, FourH);
    for (int l = 1; l < Ld; l++)
        transpose_tf32<<<dim3(FourH / 32, Hd / 32), dim3(32, 8)>>>(
            Wxs + (size_t)(l - 1) * Hd * FourH,
            wtf + (size_t)Din * FourH + (size_t)(l - 1) * Hd * FourH,
            Hd, FourH);

    dim3 pgrid(FourH / 256, Mrows / 128);   // 16 x 128

    for (int l = 0; l < Ld; l++) {
        const float* A  = (l == 0) ? xtf : (((l - 1) & 1) == 0 ? hs0 : hs1);
        const float* Wt = (l == 0) ? wtf : (wtf + (size_t)Din * FourH
                                               + (size_t)(l - 1) * Hd * FourH);
        int K  = (l == 0) ? Din : Hd;
        int st = (l == 0) ? Din : Bsz * Hd;
        int sb = (l == 0) ? Tlen * Din : Hd;

        proj_gemm_tc<<<pgrid, 512, PROJ_SMEM>>>(A, st, sb, K, Wt,
                                                bs + (size_t)l * FourH);

        cudaMemsetAsync(sync_addr, 0, 128 * 32 * sizeof(unsigned));

        const float* Wh = Whs + (size_t)l * Hd * FourH;
        lstm_layer_tc<<<128, 512, REC_SMEM>>>(Wh, l & 1, (l < Ld - 1) ? 1 : 0);
    }

    head_kernel<<<Bsz, 320>>>(Wc, bc, out);
}